// round 5
// baseline (speedup 1.0000x reference)
#include <cuda_runtime.h>
#include <cuda.h>
#include <cstdint>

// ============================================================================
// PHM8Linear: out[131072,512] = X[131072,512] @ H[512,512]^T + bias
// H[a*64+b][c*64+d] = sum_i A[i,a,c] * S[i,b,d]
// tcgen05 TF32 SS GEMM. Tile M=256 x N=256 per CTA, 3-stage TMA pipeline.
// Cluster-2: blockIdx pair {2m,2m+1} shares the X tile (rank = nb), each rank
// multicasts its 16KB X half-slice to both CTAs. Warp-specialized:
// warp0 = MMA dispatcher (never waits completion), warp1 = TMA producer.
// X fed raw fp32 (HW tf32 truncation); H pre-rounded RN->tf32 in build_H.
// ============================================================================

#define N_F    512
#define KC     32          // K elems per chunk = 128 bytes = SW128 row
#define MT     256         // M rows per CTA
#define NT     256         // N cols per CTA
#define NSTAGE 3
#define NITER  (N_F / KC)  // 16

__device__ float g_H[N_F * N_F];   // precomputed H (tf32-rounded fp32 bits)

#if defined(__CUDA_ARCH__) && (defined(__CUDA_ARCH_FEAT_SM103_ALL) || \
    defined(__CUDA_ARCH_FEAT_SM100_ALL) || defined(__CUDA_ARCH_FEAT_SM101_ALL))
#define HAS_TCGEN05 1
#else
#define HAS_TCGEN05 0
#endif

// ---------------- smem layout (dynamic), tcgen05 path ----------------
#define OFF_TPTR   0
#define OFF_FULL(s) (8 + 8 * (s))
#define OFF_DONE(s) (40 + 8 * (s))
#define OFF_EPI     64
#define OFF_STG(s)  (1024 + (s) * 65536)   // X 32KB @ +0, H 32KB @ +32768
#define SMEM_BYTES  (1024 + NSTAGE * 65536)
#define EXPECT_BYTES 65536u

// idesc: kind::tf32, D=F32(1<<4), A=TF32(2<<7), B=TF32(2<<10), N=256, M=128
#define IDESC_TF32_N256 ((1u << 4) | (2u << 7) | (2u << 10) | ((256u / 8u) << 17) | ((128u / 16u) << 24))

// K-major SW128 smem descriptor base: layout=SW128(2), version=1, SBO=64, LBO=1
static __device__ __host__ constexpr uint64_t DESC_BASE_SW128 =
    (uint64_t(2) << 61) | (uint64_t(1) << 46) | (uint64_t(64) << 32) | (uint64_t(1) << 16);

__device__ __forceinline__ uint32_t s2u(const void* p) {
    uint32_t a;
    asm("{ .reg .u64 t; cvta.to.shared.u64 t, %1; cvt.u32.u64 %0, t; }" : "=r"(a) : "l"(p));
    return a;
}

#define MBAR_INIT(addr, cnt) \
    asm volatile("mbarrier.init.shared.b64 [%0], %1;" :: "r"(addr), "r"(cnt) : "memory")

#define MBAR_EXPECT_TX(addr, bytes) \
    asm volatile("mbarrier.arrive.expect_tx.shared.b64 _, [%0], %1;" :: "r"(addr), "r"(bytes) : "memory")

#define MBAR_WAIT(addr, parity) do {                                           \
    uint32_t _mb = (addr); uint32_t _ph = (parity); uint32_t _dn;              \
    asm volatile("{\n\t.reg .pred p;\n\t"                                      \
        "mbarrier.try_wait.parity.acquire.cta.shared::cta.b64 p, [%1], %2;\n\t"\
        "selp.b32 %0, 1, 0, p;\n\t}" : "=r"(_dn) : "r"(_mb), "r"(_ph) : "memory"); \
    while (!_dn) {                                                             \
        asm volatile("{\n\t.reg .pred p;\n\t"                                  \
            "mbarrier.try_wait.parity.acquire.cta.shared::cta.b64 p, [%1], %2, 0x989680;\n\t" \
            "selp.b32 %0, 1, 0, p;\n\t}" : "=r"(_dn) : "r"(_mb), "r"(_ph) : "memory"); \
    }                                                                          \
} while (0)

#define TMA2D(smem, map, cx, cy, mbar)                                         \
    asm volatile("cp.async.bulk.tensor.2d.shared::cta.global.tile.mbarrier::complete_tx::bytes " \
        "[%0], [%1, {%2, %3}], [%4];"                                          \
        :: "r"(smem), "l"(map), "r"(cx), "r"(cy), "r"(mbar) : "memory")

#define TMA2D_MCAST(smem, map, cx, cy, mbar, mask)                             \
    asm volatile("cp.async.bulk.tensor.2d.shared::cluster.global.tile.mbarrier::complete_tx::bytes.multicast::cluster " \
        "[%0], [%1, {%2, %3}], [%4], %5;"                                      \
        :: "r"(smem), "l"(map), "r"(cx), "r"(cy), "r"(mbar), "h"((uint16_t)(mask)) : "memory")

#define CLUSTER_SYNC() do {                                                    \
    asm volatile("barrier.cluster.arrive.aligned;" ::: "memory");              \
    asm volatile("barrier.cluster.wait.aligned;" ::: "memory");                \
} while (0)

// ---------------------------------------------------------------------------
// H precompute: H[r=a*64+b][k=c*64+d] = sum_i A[i,a,c]*S[i,b,d], RN->tf32
// ---------------------------------------------------------------------------
__global__ void build_H(const float* __restrict__ A, const float* __restrict__ S) {
    int r = blockIdx.x;     // 0..511
    int k = threadIdx.x;    // 0..511
    int a = r >> 6, bb = r & 63, c = k >> 6, d = k & 63;
    float acc = 0.f;
#pragma unroll
    for (int i = 0; i < 8; i++)
        acc = fmaf(A[i * 64 + a * 8 + c], S[i * 4096 + bb * 64 + d], acc);
    uint32_t t;
    asm("cvt.rna.tf32.f32 %0, %1;" : "=r"(t) : "f"(acc));
    g_H[r * N_F + k] = __uint_as_float(t);
}

// ---------------------------------------------------------------------------
// Main GEMM kernel — body depends on arch-feature pass
// ---------------------------------------------------------------------------
__global__ void __launch_bounds__(256, 1) __cluster_dims__(2, 1, 1) phm_gemm(
    const float* __restrict__ x,
    const float* __restrict__ bias, float* __restrict__ out,
    const __grid_constant__ CUtensorMap mx,
    const __grid_constant__ CUtensorMap mh)
{
    int bx = blockIdx.x;
    int m0 = (bx >> 1) * MT;      // 256-row M tile (shared by cluster pair)
    int nb = bx & 1;              // N half: cols nb*256 .. +255 (== cluster rank)

#if HAS_TCGEN05
    // =================== tcgen05 TF32 path (sm_103a) =====================
    (void)x;
    extern __shared__ char smem_raw[];
    uint32_t sb = s2u(smem_raw);
    int tid = threadIdx.x, wid = tid >> 5, lid = tid & 31;

    if (wid == 0) {
        asm volatile("tcgen05.alloc.cta_group::1.sync.aligned.shared::cta.b32 [%0], %1;"
                     :: "r"(sb + OFF_TPTR), "r"(512) : "memory");
        asm volatile("tcgen05.relinquish_alloc_permit.cta_group::1.sync.aligned;");
    }
    if (tid == 0) {
#pragma unroll
        for (int s = 0; s < NSTAGE; s++) {
            MBAR_INIT(sb + OFF_FULL(s), 1);   // 1 arrive (local expect_tx)
            MBAR_INIT(sb + OFF_DONE(s), 2);   // 2 arrives (both CTAs' mcast commits)
        }
        MBAR_INIT(sb + OFF_EPI, 1);
    }
    __syncthreads();
    uint32_t tmem;
    asm volatile("ld.shared.b32 %0, [%1];" : "=r"(tmem) : "r"(sb + OFF_TPTR));

    // Both CTAs' mbarriers must be live before any multicast TMA / commit.
    CLUSTER_SYNC();

    if (tid == 32) {
        // ---------------- producer warp ----------------
        // X tile is shared across the pair: rank nb loads rows
        // [m0 + nb*128, +128) (16KB) and multicasts to both CTAs.
        // H half (rows nb*256, 32KB) is per-CTA, unicast.
#pragma unroll
        for (int s = 0; s < NSTAGE; s++) {
            MBAR_EXPECT_TX(sb + OFF_FULL(s), EXPECT_BYTES);
            TMA2D_MCAST(sb + OFF_STG(s) + nb * 16384, &mx, s * KC, m0 + nb * 128,
                        sb + OFF_FULL(s), 3);
            TMA2D(sb + OFF_STG(s) + 32768, &mh, s * KC, nb * NT, sb + OFF_FULL(s));
        }
        for (int kc = NSTAGE; kc < NITER; kc++) {
            int s = kc % NSTAGE;
            // stage s last used by chunk kc-NSTAGE; wait both CTAs drained it
            MBAR_WAIT(sb + OFF_DONE(s), ((kc - NSTAGE) / NSTAGE) & 1);
            MBAR_EXPECT_TX(sb + OFF_FULL(s), EXPECT_BYTES);
            TMA2D_MCAST(sb + OFF_STG(s) + nb * 16384, &mx, kc * KC, m0 + nb * 128,
                        sb + OFF_FULL(s), 3);
            TMA2D(sb + OFF_STG(s) + 32768, &mh, kc * KC, nb * NT, sb + OFF_FULL(s));
        }
    } else if (tid == 0) {
        // ---------------- MMA dispatch warp (never waits completion) -----
        for (int kc = 0; kc < NITER; kc++) {
            int s = kc % NSTAGE;
            MBAR_WAIT(sb + OFF_FULL(s), (kc / NSTAGE) & 1);

            uint64_t ax0 = DESC_BASE_SW128 | (((sb + OFF_STG(s))         >> 4) & 0x3FFF);
            uint64_t ax1 = DESC_BASE_SW128 | (((sb + OFF_STG(s) + 16384) >> 4) & 0x3FFF);
            uint64_t bh  = DESC_BASE_SW128 | (((sb + OFF_STG(s) + 32768) >> 4) & 0x3FFF);
#pragma unroll
            for (int ks = 0; ks < 4; ks++) {  // K=8 per MMA, +2 (32B) per step
                uint32_t en = (kc | ks) ? 1u : 0u;
                asm volatile(
                    "{\n\t.reg .pred p;\n\tsetp.ne.u32 p, %5, 0;\n\t"
                    "tcgen05.mma.cta_group::1.kind::tf32 [%0], %1, %2, %3, {%4,%4,%4,%4}, p;\n\t}"
                    :: "r"(tmem), "l"(ax0 + 2 * ks), "l"(bh + 2 * ks),
                       "r"(IDESC_TF32_N256), "r"(0u), "r"(en) : "memory");
                asm volatile(
                    "{\n\t.reg .pred p;\n\tsetp.ne.u32 p, %5, 0;\n\t"
                    "tcgen05.mma.cta_group::1.kind::tf32 [%0], %1, %2, %3, {%4,%4,%4,%4}, p;\n\t}"
                    :: "r"(tmem + 256), "l"(ax1 + 2 * ks), "l"(bh + 2 * ks),
                       "r"(IDESC_TF32_N256), "r"(0u), "r"(en) : "memory");
            }
            // buffer-drain signal for chunk kc -> BOTH CTAs' done(s)
            asm volatile(
                "tcgen05.commit.cta_group::1.mbarrier::arrive::one.shared::cluster.multicast::cluster.b64 [%0], %1;"
                :: "r"(sb + OFF_DONE(s)), "h"((uint16_t)3) : "memory");
        }
        // all MMAs of this CTA complete -> epilogue barrier
        asm volatile(
            "tcgen05.commit.cta_group::1.mbarrier::arrive::one.shared::cluster.b64 [%0];"
            :: "r"(sb + OFF_EPI) : "memory");
    }

    // All threads: wait for all MMAs, then read TMEM.
    MBAR_WAIT(sb + OFF_EPI, 0);
    asm volatile("tcgen05.fence::after_thread_sync;" ::: "memory");

    // Epilogue: warps 0-3 -> D0 (rows m0+0..127, tmem cols 0..255),
    //           warps 4-7 -> D1 (rows m0+128..255, tmem cols 256..511)
    int sp = wid & 3;
    int half = wid >> 2;
    size_t row = (size_t)(m0 + half * 128 + sp * 32 + lid);
    float* orow = out + row * N_F + nb * NT;
    uint32_t tb = tmem + half * 256;
#pragma unroll
    for (int ch = 0; ch < 8; ch++) {
        int c0 = ch * 32;
        uint32_t r[32];
        asm volatile(
            "tcgen05.ld.sync.aligned.32x32b.x32.b32 "
            "{%0, %1, %2, %3, %4, %5, %6, %7, "
            " %8, %9, %10, %11, %12, %13, %14, %15, "
            " %16, %17, %18, %19, %20, %21, %22, %23, "
            " %24, %25, %26, %27, %28, %29, %30, %31}, [%32];"
            : "=r"(r[0]),  "=r"(r[1]),  "=r"(r[2]),  "=r"(r[3]),
              "=r"(r[4]),  "=r"(r[5]),  "=r"(r[6]),  "=r"(r[7]),
              "=r"(r[8]),  "=r"(r[9]),  "=r"(r[10]), "=r"(r[11]),
              "=r"(r[12]), "=r"(r[13]), "=r"(r[14]), "=r"(r[15]),
              "=r"(r[16]), "=r"(r[17]), "=r"(r[18]), "=r"(r[19]),
              "=r"(r[20]), "=r"(r[21]), "=r"(r[22]), "=r"(r[23]),
              "=r"(r[24]), "=r"(r[25]), "=r"(r[26]), "=r"(r[27]),
              "=r"(r[28]), "=r"(r[29]), "=r"(r[30]), "=r"(r[31])
            : "r"(tb + c0));
        asm volatile("tcgen05.wait::ld.sync.aligned;" ::: "memory");
#pragma unroll
        for (int j = 0; j < 8; j++) {
            float4 bv = *reinterpret_cast<const float4*>(bias + nb * NT + c0 + j * 4);
            float4 v;
            v.x = __uint_as_float(r[j * 4 + 0]) + bv.x;
            v.y = __uint_as_float(r[j * 4 + 1]) + bv.y;
            v.z = __uint_as_float(r[j * 4 + 2]) + bv.z;
            v.w = __uint_as_float(r[j * 4 + 3]) + bv.w;
            *reinterpret_cast<float4*>(orow + c0 + j * 4) = v;
        }
    }
    __syncthreads();
    // No CTA may exit while the peer could still multicast into our smem.
    CLUSTER_SYNC();
    if (wid == 0) {
        asm volatile("tcgen05.dealloc.cta_group::1.sync.aligned.b32 %0, %1;"
                     :: "r"(tmem), "r"(512));
    }

#else
    // =================== SIMT fp32 fallback (non-'a' pass) ================
    (void)mx; (void)mh;
    extern __shared__ char smem_raw[];
    float* Xs = reinterpret_cast<float*>(smem_raw);          // [128][33]
    float* Hs = Xs + 128 * 33;                               // [64][33]

    int tid = threadIdx.x;
    int ty = tid >> 4, tx = tid & 15;

    for (int half = 0; half < 2; half++) {
        int m0h = m0 + half * 128;
        for (int nc = 0; nc < 4; nc++) {
            int col0 = nb * NT + nc * 64;
            float acc[8][4];
#pragma unroll
            for (int i = 0; i < 8; i++)
#pragma unroll
                for (int j = 0; j < 4; j++) acc[i][j] = 0.f;

            for (int kb = 0; kb < NITER; kb++) {
#pragma unroll
                for (int it = 0; it < 16; it++) {
                    int idx = tid + it * 256;
                    int r = idx >> 5, k = idx & 31;
                    Xs[r * 33 + k] = x[(size_t)(m0h + r) * N_F + kb * 32 + k];
                }
#pragma unroll
                for (int it = 0; it < 8; it++) {
                    int idx = tid + it * 256;
                    int r = idx >> 5, k = idx & 31;
                    Hs[r * 33 + k] = g_H[(size_t)(col0 + r) * N_F + kb * 32 + k];
                }
                __syncthreads();
#pragma unroll
                for (int k = 0; k < 32; k++) {
                    float a8[8], b4[4];
#pragma unroll
                    for (int i = 0; i < 8; i++) a8[i] = Xs[(ty * 8 + i) * 33 + k];
#pragma unroll
                    for (int j = 0; j < 4; j++) b4[j] = Hs[(tx * 4 + j) * 33 + k];
#pragma unroll
                    for (int i = 0; i < 8; i++)
#pragma unroll
                        for (int j = 0; j < 4; j++)
                            acc[i][j] = fmaf(a8[i], b4[j], acc[i][j]);
                }
                __syncthreads();
            }
#pragma unroll
            for (int i = 0; i < 8; i++)
#pragma unroll
                for (int j = 0; j < 4; j++) {
                    int col = col0 + tx * 4 + j;
                    out[(size_t)(m0h + ty * 8 + i) * N_F + col] = acc[i][j] + bias[col];
                }
        }
    }
#endif
}

// ---------------------------------------------------------------------------
// Host launcher
// ---------------------------------------------------------------------------
typedef CUresult (*PFN_encodeTiled)(
    CUtensorMap*, CUtensorMapDataType, cuuint32_t, void*,
    const cuuint64_t*, const cuuint64_t*, const cuuint32_t*, const cuuint32_t*,
    CUtensorMapInterleave, CUtensorMapSwizzle, CUtensorMapL2promotion,
    CUtensorMapFloatOOBfill);

extern "C" void kernel_launch(void* const* d_in, const int* in_sizes, int n_in,
                              void* d_out, int out_size) {
    const float* x    = (const float*)d_in[0];
    const float* A    = (const float*)d_in[1];
    const float* S    = (const float*)d_in[2];
    const float* bias = (const float*)d_in[3];
    float* out = (float*)d_out;

    long Mrows = (long)in_sizes[0] / N_F;   // 131072

    build_H<<<N_F, N_F>>>(A, S);

    void* hptr = nullptr;
    cudaGetSymbolAddress(&hptr, g_H);

    // Resolve cuTensorMapEncodeTiled via the runtime (no -lcuda needed).
    PFN_encodeTiled enc = nullptr;
    {
        cudaDriverEntryPointQueryResult st;
        cudaGetDriverEntryPointByVersion("cuTensorMapEncodeTiled", (void**)&enc,
                                         12050, cudaEnableDefault, &st);
    }

    CUtensorMap mx{}, mh{};
    if (enc) {
        {
            cuuint64_t dims[2]    = {(cuuint64_t)N_F, (cuuint64_t)Mrows};
            cuuint64_t strides[1] = {(cuuint64_t)N_F * 4};
            cuuint32_t box[2]     = {KC, 128};       // 128B x 128 rows (X half-slice)
            cuuint32_t es[2]      = {1, 1};
            enc(&mx, CU_TENSOR_MAP_DATA_TYPE_FLOAT32, 2, (void*)x,
                dims, strides, box, es,
                CU_TENSOR_MAP_INTERLEAVE_NONE, CU_TENSOR_MAP_SWIZZLE_128B,
                CU_TENSOR_MAP_L2_PROMOTION_L2_128B, CU_TENSOR_MAP_FLOAT_OOB_FILL_NONE);
        }
        {
            cuuint64_t dims[2]    = {(cuuint64_t)N_F, (cuuint64_t)N_F};
            cuuint64_t strides[1] = {(cuuint64_t)N_F * 4};
            cuuint32_t box[2]     = {KC, NT};        // 128B x 256 rows
            cuuint32_t es[2]      = {1, 1};
            enc(&mh, CU_TENSOR_MAP_DATA_TYPE_FLOAT32, 2, hptr,
                dims, strides, box, es,
                CU_TENSOR_MAP_INTERLEAVE_NONE, CU_TENSOR_MAP_SWIZZLE_128B,
                CU_TENSOR_MAP_L2_PROMOTION_L2_128B, CU_TENSOR_MAP_FLOAT_OOB_FILL_NONE);
        }
    }

    cudaFuncSetAttribute(phm_gemm, cudaFuncAttributeMaxDynamicSharedMemorySize, SMEM_BYTES);
    phm_gemm<<<(int)(Mrows / MT) * 2, 256, SMEM_BYTES>>>(x, bias, out, mx, mh);
}

// round 6
// speedup vs baseline: 1.0864x; 1.0864x over previous
#include <cuda_runtime.h>
#include <cuda.h>
#include <cstdint>

// ============================================================================
// PHM8Linear: out[131072,512] = X[131072,512] @ H[512,512]^T + bias
// H[a*64+b][c*64+d] = sum_i A[i,a,c] * S[i,b,d]
// tcgen05 TF32 SS GEMM. PERSISTENT: grid=148, each CTA loops over tiles
// (M=256 x N=256). Stage ring (3 x 64KB) runs continuously across tiles.
// warp0 lane0 = MMA dispatcher, warp1 lane0 = TMA producer,
// warps 2-7 = epilogue (overlapped with next tile's TMA prefetch).
// X fed raw fp32 (HW tf32 truncation); H pre-rounded RN->tf32 in build_H.
// ============================================================================

#define N_F    512
#define KC     32          // K elems per chunk = 128 bytes = SW128 row
#define MT     256         // M rows per tile
#define NT     256         // N cols per tile
#define NSTAGE 3
#define NITER  (N_F / KC)  // 16
#define GRID   148

__device__ float g_H[N_F * N_F];   // precomputed H (tf32-rounded fp32 bits)

#if defined(__CUDA_ARCH__) && (defined(__CUDA_ARCH_FEAT_SM103_ALL) || \
    defined(__CUDA_ARCH_FEAT_SM100_ALL) || defined(__CUDA_ARCH_FEAT_SM101_ALL))
#define HAS_TCGEN05 1
#else
#define HAS_TCGEN05 0
#endif

// ---------------- smem layout (dynamic), tcgen05 path ----------------
#define OFF_TPTR    0
#define OFF_FULL(s) (8 + 8 * (s))
#define OFF_DONE(s) (40 + 8 * (s))
#define OFF_EPI     64
#define OFF_DFREE   72
#define OFF_STG(s)  (1024 + (s) * 65536)   // X 32KB @ +0, H 32KB @ +32768
#define SMEM_BYTES  (1024 + NSTAGE * 65536)
#define EXPECT_BYTES 65536u

// idesc: kind::tf32, D=F32(1<<4), A=TF32(2<<7), B=TF32(2<<10), N=256, M=128
#define IDESC_TF32_N256 ((1u << 4) | (2u << 7) | (2u << 10) | ((256u / 8u) << 17) | ((128u / 16u) << 24))

// K-major SW128 smem descriptor base: layout=SW128(2), version=1, SBO=64, LBO=1
static __device__ __host__ constexpr uint64_t DESC_BASE_SW128 =
    (uint64_t(2) << 61) | (uint64_t(1) << 46) | (uint64_t(64) << 32) | (uint64_t(1) << 16);

__device__ __forceinline__ uint32_t s2u(const void* p) {
    uint32_t a;
    asm("{ .reg .u64 t; cvta.to.shared.u64 t, %1; cvt.u32.u64 %0, t; }" : "=r"(a) : "l"(p));
    return a;
}

#define MBAR_INIT(addr, cnt) \
    asm volatile("mbarrier.init.shared.b64 [%0], %1;" :: "r"(addr), "r"(cnt) : "memory")

#define MBAR_ARRIVE(addr) \
    asm volatile("mbarrier.arrive.shared.b64 _, [%0];" :: "r"(addr) : "memory")

#define MBAR_EXPECT_TX(addr, bytes) \
    asm volatile("mbarrier.arrive.expect_tx.shared.b64 _, [%0], %1;" :: "r"(addr), "r"(bytes) : "memory")

#define MBAR_WAIT(addr, parity) do {                                           \
    uint32_t _mb = (addr); uint32_t _ph = (parity); uint32_t _dn;              \
    asm volatile("{\n\t.reg .pred p;\n\t"                                      \
        "mbarrier.try_wait.parity.acquire.cta.shared::cta.b64 p, [%1], %2;\n\t"\
        "selp.b32 %0, 1, 0, p;\n\t}" : "=r"(_dn) : "r"(_mb), "r"(_ph) : "memory"); \
    while (!_dn) {                                                             \
        asm volatile("{\n\t.reg .pred p;\n\t"                                  \
            "mbarrier.try_wait.parity.acquire.cta.shared::cta.b64 p, [%1], %2, 0x989680;\n\t" \
            "selp.b32 %0, 1, 0, p;\n\t}" : "=r"(_dn) : "r"(_mb), "r"(_ph) : "memory"); \
    }                                                                          \
} while (0)

#define TMA2D(smem, map, cx, cy, mbar)                                         \
    asm volatile("cp.async.bulk.tensor.2d.shared::cta.global.tile.mbarrier::complete_tx::bytes " \
        "[%0], [%1, {%2, %3}], [%4];"                                          \
        :: "r"(smem), "l"(map), "r"(cx), "r"(cy), "r"(mbar) : "memory")

// ---------------------------------------------------------------------------
// H precompute: H[r=a*64+b][k=c*64+d] = sum_i A[i,a,c]*S[i,b,d], RN->tf32
// ---------------------------------------------------------------------------
__global__ void build_H(const float* __restrict__ A, const float* __restrict__ S) {
    int r = blockIdx.x;     // 0..511
    int k = threadIdx.x;    // 0..511
    int a = r >> 6, bb = r & 63, c = k >> 6, d = k & 63;
    float acc = 0.f;
#pragma unroll
    for (int i = 0; i < 8; i++)
        acc = fmaf(A[i * 64 + a * 8 + c], S[i * 4096 + bb * 64 + d], acc);
    uint32_t t;
    asm("cvt.rna.tf32.f32 %0, %1;" : "=r"(t) : "f"(acc));
    g_H[r * N_F + k] = __uint_as_float(t);
}

// ---------------------------------------------------------------------------
// Main GEMM kernel — body depends on arch-feature pass
// ---------------------------------------------------------------------------
__global__ void __launch_bounds__(256, 1) phm_gemm(
    const float* __restrict__ x,
    const float* __restrict__ bias, float* __restrict__ out,
    int ntiles,
    const __grid_constant__ CUtensorMap mx,
    const __grid_constant__ CUtensorMap mh)
{
    int bid = blockIdx.x;

#if HAS_TCGEN05
    // =================== tcgen05 TF32 path (sm_103a) =====================
    (void)x;
    extern __shared__ char smem_raw[];
    uint32_t sb = s2u(smem_raw);
    int tid = threadIdx.x, wid = tid >> 5, lid = tid & 31;

    if (wid == 0) {
        asm volatile("tcgen05.alloc.cta_group::1.sync.aligned.shared::cta.b32 [%0], %1;"
                     :: "r"(sb + OFF_TPTR), "r"(512) : "memory");
        asm volatile("tcgen05.relinquish_alloc_permit.cta_group::1.sync.aligned;");
    }
    if (tid == 0) {
#pragma unroll
        for (int s = 0; s < NSTAGE; s++) {
            MBAR_INIT(sb + OFF_FULL(s), 1);
            MBAR_INIT(sb + OFF_DONE(s), 1);
        }
        MBAR_INIT(sb + OFF_EPI, 1);
        MBAR_INIT(sb + OFF_DFREE, 6);      // one arrive per epilogue warp
    }
    __syncthreads();
    uint32_t tmem;
    asm volatile("ld.shared.b32 %0, [%1];" : "=r"(tmem) : "r"(sb + OFF_TPTR));

    if (wid == 0) {
        if (lid == 0) {
            // ---------------- MMA dispatcher ----------------
            uint64_t ax0[NSTAGE], ax1[NSTAGE], bh[NSTAGE];
#pragma unroll
            for (int s = 0; s < NSTAGE; s++) {
                ax0[s] = DESC_BASE_SW128 | (((sb + OFF_STG(s))         >> 4) & 0x3FFF);
                ax1[s] = DESC_BASE_SW128 | (((sb + OFF_STG(s) + 16384) >> 4) & 0x3FFF);
                bh[s]  = DESC_BASE_SW128 | (((sb + OFF_STG(s) + 32768) >> 4) & 0x3FFF);
            }
            int cs = 0, ph = 0;     // stage cursor + phase
            int dfph = 0;
            for (int g = bid; g < ntiles; g += GRID) {
                if (g != bid) {      // D reused: wait epilogue of previous tile
                    MBAR_WAIT(sb + OFF_DFREE, dfph);
                    dfph ^= 1;
                    asm volatile("tcgen05.fence::after_thread_sync;" ::: "memory");
                }
                for (int kc = 0; kc < NITER; kc++) {
                    MBAR_WAIT(sb + OFF_FULL(cs), ph);
#pragma unroll
                    for (int ks = 0; ks < 4; ks++) {  // K=8 per MMA, +2 per step
                        uint32_t en = (kc | ks) ? 1u : 0u;
                        asm volatile(
                            "{\n\t.reg .pred p;\n\tsetp.ne.u32 p, %5, 0;\n\t"
                            "tcgen05.mma.cta_group::1.kind::tf32 [%0], %1, %2, %3, {%4,%4,%4,%4}, p;\n\t}"
                            :: "r"(tmem), "l"(ax0[cs] + 2 * ks), "l"(bh[cs] + 2 * ks),
                               "r"(IDESC_TF32_N256), "r"(0u), "r"(en) : "memory");
                        asm volatile(
                            "{\n\t.reg .pred p;\n\tsetp.ne.u32 p, %5, 0;\n\t"
                            "tcgen05.mma.cta_group::1.kind::tf32 [%0], %1, %2, %3, {%4,%4,%4,%4}, p;\n\t}"
                            :: "r"(tmem + 256), "l"(ax1[cs] + 2 * ks), "l"(bh[cs] + 2 * ks),
                               "r"(IDESC_TF32_N256), "r"(0u), "r"(en) : "memory");
                    }
                    asm volatile(
                        "tcgen05.commit.cta_group::1.mbarrier::arrive::one.shared::cluster.b64 [%0];"
                        :: "r"(sb + OFF_DONE(cs)) : "memory");
                    if (++cs == NSTAGE) { cs = 0; ph ^= 1; }
                }
                // tile complete -> release epilogue
                asm volatile(
                    "tcgen05.commit.cta_group::1.mbarrier::arrive::one.shared::cluster.b64 [%0];"
                    :: "r"(sb + OFF_EPI) : "memory");
            }
        }
    } else if (wid == 1) {
        if (lid == 0) {
            // ---------------- TMA producer (free-running across tiles) -----
            int cs = 0, ph = 0;
            int filled = 0;
            for (int g = bid; g < ntiles; g += GRID) {
                int m0 = (g >> 1) * MT;
                int nb = g & 1;
                for (int kc = 0; kc < NITER; kc++) {
                    if (filled >= NSTAGE)
                        MBAR_WAIT(sb + OFF_DONE(cs), ph ^ 1);  // stage drained
                    MBAR_EXPECT_TX(sb + OFF_FULL(cs), EXPECT_BYTES);
                    TMA2D(sb + OFF_STG(cs),         &mx, kc * KC, m0,      sb + OFF_FULL(cs));
                    TMA2D(sb + OFF_STG(cs) + 32768, &mh, kc * KC, nb * NT, sb + OFF_FULL(cs));
                    filled++;
                    if (++cs == NSTAGE) { cs = 0; ph ^= 1; }
                }
            }
        }
    } else {
        // ---------------- epilogue warps (2..7) ----------------
        // units (half, sp): warp4 -> sp0 both halves, warp5 -> sp1 both halves,
        // warp2/6 -> sp2 half0/1, warp3/7 -> sp3 half0/1.
        int sp = wid & 3;
        int nu, h0;
        if (sp < 2)      { nu = 2; h0 = 0; }          // warps 4,5
        else             { nu = 1; h0 = (wid >= 6); } // warps 2,3,6,7

        int eph = 0;
        for (int g = bid; g < ntiles; g += GRID) {
            MBAR_WAIT(sb + OFF_EPI, eph);
            eph ^= 1;
            asm volatile("tcgen05.fence::after_thread_sync;" ::: "memory");

            int m0 = (g >> 1) * MT;
            int nb = g & 1;
            for (int u = 0; u < nu; u++) {
                int half = h0 + u;
                size_t row = (size_t)(m0 + half * 128 + sp * 32 + lid);
                float* orow = out + row * N_F + nb * NT;
                uint32_t tb = tmem + half * 256;
#pragma unroll
                for (int ch = 0; ch < 8; ch++) {
                    int c0 = ch * 32;
                    uint32_t r[32];
                    asm volatile(
                        "tcgen05.ld.sync.aligned.32x32b.x32.b32 "
                        "{%0, %1, %2, %3, %4, %5, %6, %7, "
                        " %8, %9, %10, %11, %12, %13, %14, %15, "
                        " %16, %17, %18, %19, %20, %21, %22, %23, "
                        " %24, %25, %26, %27, %28, %29, %30, %31}, [%32];"
                        : "=r"(r[0]),  "=r"(r[1]),  "=r"(r[2]),  "=r"(r[3]),
                          "=r"(r[4]),  "=r"(r[5]),  "=r"(r[6]),  "=r"(r[7]),
                          "=r"(r[8]),  "=r"(r[9]),  "=r"(r[10]), "=r"(r[11]),
                          "=r"(r[12]), "=r"(r[13]), "=r"(r[14]), "=r"(r[15]),
                          "=r"(r[16]), "=r"(r[17]), "=r"(r[18]), "=r"(r[19]),
                          "=r"(r[20]), "=r"(r[21]), "=r"(r[22]), "=r"(r[23]),
                          "=r"(r[24]), "=r"(r[25]), "=r"(r[26]), "=r"(r[27]),
                          "=r"(r[28]), "=r"(r[29]), "=r"(r[30]), "=r"(r[31])
                        : "r"(tb + c0));
                    asm volatile("tcgen05.wait::ld.sync.aligned;" ::: "memory");
#pragma unroll
                    for (int j = 0; j < 8; j++) {
                        float4 bv = *reinterpret_cast<const float4*>(bias + nb * NT + c0 + j * 4);
                        float4 v;
                        v.x = __uint_as_float(r[j * 4 + 0]) + bv.x;
                        v.y = __uint_as_float(r[j * 4 + 1]) + bv.y;
                        v.z = __uint_as_float(r[j * 4 + 2]) + bv.z;
                        v.w = __uint_as_float(r[j * 4 + 3]) + bv.w;
                        *reinterpret_cast<float4*>(orow + c0 + j * 4) = v;
                    }
                }
            }
            // D fully read -> let dispatcher start next tile
            asm volatile("tcgen05.fence::before_thread_sync;" ::: "memory");
            if (lid == 0) MBAR_ARRIVE(sb + OFF_DFREE);
        }
    }

    __syncthreads();
    if (wid == 0) {
        asm volatile("tcgen05.dealloc.cta_group::1.sync.aligned.b32 %0, %1;"
                     :: "r"(tmem), "r"(512));
    }

#else
    // =================== SIMT fp32 fallback (non-'a' pass) ================
    (void)mx; (void)mh;
    extern __shared__ char smem_raw[];
    float* Xs = reinterpret_cast<float*>(smem_raw);          // [128][33]
    float* Hs = Xs + 128 * 33;                               // [64][33]

    int tid = threadIdx.x;
    int ty = tid >> 4, tx = tid & 15;

    for (int g = bid; g < ntiles; g += GRID) {
        int m0 = (g >> 1) * MT;
        int nb = g & 1;
        for (int half = 0; half < 2; half++) {
            int m0h = m0 + half * 128;
            for (int nc = 0; nc < 4; nc++) {
                int col0 = nb * NT + nc * 64;
                float acc[8][4];
#pragma unroll
                for (int i = 0; i < 8; i++)
#pragma unroll
                    for (int j = 0; j < 4; j++) acc[i][j] = 0.f;

                for (int kb = 0; kb < NITER; kb++) {
#pragma unroll
                    for (int it = 0; it < 16; it++) {
                        int idx = tid + it * 256;
                        int r = idx >> 5, k = idx & 31;
                        Xs[r * 33 + k] = x[(size_t)(m0h + r) * N_F + kb * 32 + k];
                    }
#pragma unroll
                    for (int it = 0; it < 8; it++) {
                        int idx = tid + it * 256;
                        int r = idx >> 5, k = idx & 31;
                        Hs[r * 33 + k] = g_H[(size_t)(col0 + r) * N_F + kb * 32 + k];
                    }
                    __syncthreads();
#pragma unroll
                    for (int k = 0; k < 32; k++) {
                        float a8[8], b4[4];
#pragma unroll
                        for (int i = 0; i < 8; i++) a8[i] = Xs[(ty * 8 + i) * 33 + k];
#pragma unroll
                        for (int j = 0; j < 4; j++) b4[j] = Hs[(tx * 4 + j) * 33 + k];
#pragma unroll
                        for (int i = 0; i < 8; i++)
#pragma unroll
                            for (int j = 0; j < 4; j++)
                                acc[i][j] = fmaf(a8[i], b4[j], acc[i][j]);
                    }
                    __syncthreads();
                }
#pragma unroll
                for (int i = 0; i < 8; i++)
#pragma unroll
                    for (int j = 0; j < 4; j++) {
                        int col = col0 + tx * 4 + j;
                        out[(size_t)(m0h + ty * 8 + i) * N_F + col] = acc[i][j] + bias[col];
                    }
            }
        }
    }
#endif
}

// ---------------------------------------------------------------------------
// Host launcher
// ---------------------------------------------------------------------------
typedef CUresult (*PFN_encodeTiled)(
    CUtensorMap*, CUtensorMapDataType, cuuint32_t, void*,
    const cuuint64_t*, const cuuint64_t*, const cuuint32_t*, const cuuint32_t*,
    CUtensorMapInterleave, CUtensorMapSwizzle, CUtensorMapL2promotion,
    CUtensorMapFloatOOBfill);

extern "C" void kernel_launch(void* const* d_in, const int* in_sizes, int n_in,
                              void* d_out, int out_size) {
    const float* x    = (const float*)d_in[0];
    const float* A    = (const float*)d_in[1];
    const float* S    = (const float*)d_in[2];
    const float* bias = (const float*)d_in[3];
    float* out = (float*)d_out;

    long Mrows = (long)in_sizes[0] / N_F;   // 131072
    int ntiles = (int)(Mrows / MT) * 2;     // 1024

    build_H<<<N_F, N_F>>>(A, S);

    void* hptr = nullptr;
    cudaGetSymbolAddress(&hptr, g_H);

    // Resolve cuTensorMapEncodeTiled via the runtime (no -lcuda needed).
    PFN_encodeTiled enc = nullptr;
    {
        cudaDriverEntryPointQueryResult st;
        cudaGetDriverEntryPointByVersion("cuTensorMapEncodeTiled", (void**)&enc,
                                         12050, cudaEnableDefault, &st);
    }

    CUtensorMap mx{}, mh{};
    if (enc) {
        {
            cuuint64_t dims[2]    = {(cuuint64_t)N_F, (cuuint64_t)Mrows};
            cuuint64_t strides[1] = {(cuuint64_t)N_F * 4};
            cuuint32_t box[2]     = {KC, MT};        // 128B x 256 rows
            cuuint32_t es[2]      = {1, 1};
            enc(&mx, CU_TENSOR_MAP_DATA_TYPE_FLOAT32, 2, (void*)x,
                dims, strides, box, es,
                CU_TENSOR_MAP_INTERLEAVE_NONE, CU_TENSOR_MAP_SWIZZLE_128B,
                CU_TENSOR_MAP_L2_PROMOTION_L2_128B, CU_TENSOR_MAP_FLOAT_OOB_FILL_NONE);
        }
        {
            cuuint64_t dims[2]    = {(cuuint64_t)N_F, (cuuint64_t)N_F};
            cuuint64_t strides[1] = {(cuuint64_t)N_F * 4};
            cuuint32_t box[2]     = {KC, NT};        // 128B x 256 rows
            cuuint32_t es[2]      = {1, 1};
            enc(&mh, CU_TENSOR_MAP_DATA_TYPE_FLOAT32, 2, hptr,
                dims, strides, box, es,
                CU_TENSOR_MAP_INTERLEAVE_NONE, CU_TENSOR_MAP_SWIZZLE_128B,
                CU_TENSOR_MAP_L2_PROMOTION_L2_128B, CU_TENSOR_MAP_FLOAT_OOB_FILL_NONE);
        }
    }

    cudaFuncSetAttribute(phm_gemm, cudaFuncAttributeMaxDynamicSharedMemorySize, SMEM_BYTES);
    phm_gemm<<<GRID, 256, SMEM_BYTES>>>(x, bias, out, ntiles, mx, mh);
}